// round 3
// baseline (speedup 1.0000x reference)
#include <cuda_runtime.h>

// ---------------------------------------------------------------------------
// CoordKAN: widths 2 -> 32 -> 32 -> 1, cubic B-splines (K=3) on uniform grid
// G=10, h=0.1, knots at (j-3)*0.1 for j=0..16, 13 basis functions per input.
//
// Key optimization: uniform-knot cubic B-spline => only 4 nonzero basis
// functions at any x, with closed-form values from the fractional coord t.
// The dense einsum (13 wide) becomes a 4-wide sparse gather.
//
// Data staging: sp*coef folded into scratch with layout [i][k][o], k-stride
// padded to 36 floats so per-thread-varying k hits distinct smem banks
// (4*dk mod 32) for the float4 (o-vectorized) loads.
// ---------------------------------------------------------------------------

#define NSAMP (512 * 512)

// scratch layout (float offsets)
#define OFF_C0   0        // [2][13][36]  = 936
#define OFF_C1   936      // [32][13][36] = 14976
#define OFF_C2   15912    // [32][16]     = 512
#define OFF_SB0  16424    // [2][32]      = 64
#define OFF_SB1  16488    // [32][32]     = 1024
#define OFF_SB2  17512    // [32]         = 32
#define OFF_BIAS 17544    // [1]
#define SCRATCH_FLOATS 17548
#define SMEM_BYTES (SCRATCH_FLOATS * 4)

__device__ float g_scratch[SCRATCH_FLOATS];

// ---------------------------------------------------------------------------
// Prep: fold sp into coef, transpose to [i][k][o] (stride-36) layout.
// ---------------------------------------------------------------------------
__global__ void prep_kernel(const float* __restrict__ coef0, const float* __restrict__ sb0,
                            const float* __restrict__ sp0,
                            const float* __restrict__ coef1, const float* __restrict__ sb1,
                            const float* __restrict__ sp1,
                            const float* __restrict__ coef2, const float* __restrict__ sb2,
                            const float* __restrict__ sp2,
                            const float* __restrict__ bias) {
    int t = threadIdx.x + blockIdx.x * blockDim.x;
    int T = blockDim.x * gridDim.x;
    // layer1 coef: (32, 32, 13) -> [i][k][o] stride 36
    for (int idx = t; idx < 32 * 13 * 32; idx += T) {
        int i = idx / (13 * 32);
        int k = (idx / 32) % 13;
        int o = idx & 31;
        g_scratch[OFF_C1 + (i * 13 + k) * 36 + o] =
            sp1[i * 32 + o] * coef1[(i * 32 + o) * 13 + k];
    }
    // layer0 coef: (2, 32, 13)
    for (int idx = t; idx < 2 * 13 * 32; idx += T) {
        int i = idx / (13 * 32);
        int k = (idx / 32) % 13;
        int o = idx & 31;
        g_scratch[OFF_C0 + (i * 13 + k) * 36 + o] =
            sp0[i * 32 + o] * coef0[(i * 32 + o) * 13 + k];
    }
    // layer2 coef: (32, 1, 13) -> [i][16]
    for (int idx = t; idx < 32 * 13; idx += T) {
        int i = idx / 13;
        int k = idx % 13;
        g_scratch[OFF_C2 + i * 16 + k] = sp2[i] * coef2[i * 13 + k];
    }
    for (int idx = t; idx < 2 * 32; idx += T)  g_scratch[OFF_SB0 + idx] = sb0[idx];
    for (int idx = t; idx < 32 * 32; idx += T) g_scratch[OFF_SB1 + idx] = sb1[idx];
    for (int idx = t; idx < 32; idx += T)      g_scratch[OFF_SB2 + idx] = sb2[idx];
    if (t == 0) g_scratch[OFF_BIAS] = bias[0];
}

// ---------------------------------------------------------------------------
// Device helpers
// ---------------------------------------------------------------------------
__device__ __forceinline__ float silu_f(float x) {
    return x * __fdividef(1.0f, 1.0f + __expf(-x));
}

struct Basis {
    float v0, v1, v2, v3;   // basis values (zeroed when out of support)
    int   k0, k1, k2, k3;   // clamped coefficient indices in [0,12]
};

__device__ __forceinline__ Basis make_basis(float x) {
    float u  = fmaf(x, 10.0f, 3.0f);
    float mf = floorf(u);
    float t  = u - mf;
    int   m  = (int)mf;
    int   j0 = m - 3;
    float t2 = t * t;
    float t3 = t2 * t;
    float omt = 1.0f - t;
    Basis b;
    b.v0 = omt * omt * omt * (1.0f / 6.0f);
    b.v1 = fmaf(3.0f, t3, fmaf(-6.0f, t2, 4.0f)) * (1.0f / 6.0f);
    b.v2 = fmaf(-3.0f, t3, fmaf(3.0f, t2, fmaf(3.0f, t, 1.0f))) * (1.0f / 6.0f);
    b.v3 = t3 * (1.0f / 6.0f);
    bool inr = (m >= 0) && (m <= 15);
    if (!inr || j0 < 0     || j0 > 12)     b.v0 = 0.0f;
    if (!inr || j0 + 1 < 0 || j0 + 1 > 12) b.v1 = 0.0f;
    if (!inr || j0 + 2 < 0 || j0 + 2 > 12) b.v2 = 0.0f;
    if (!inr || j0 + 3 < 0 || j0 + 3 > 12) b.v3 = 0.0f;
    b.k0 = min(max(j0, 0), 12);
    b.k1 = min(max(j0 + 1, 0), 12);
    b.k2 = min(max(j0 + 2, 0), 12);
    b.k3 = min(max(j0 + 3, 0), 12);
    return b;
}

// Accumulate one KAN layer with 32 outputs into acc[32].
template <int NI>
__device__ __forceinline__ void kan_layer32(const float* xin, float* acc,
                                            const float* __restrict__ sc,
                                            const float* __restrict__ ssb) {
#pragma unroll
    for (int i = 0; i < NI; i++) {
        float x    = xin[i];
        float base = silu_f(x);
        Basis bb   = make_basis(x);
        const float4* p0 = (const float4*)sc + (i * 13 + bb.k0) * 9;  // 36 floats = 9 float4
        const float4* p1 = (const float4*)sc + (i * 13 + bb.k1) * 9;
        const float4* p2 = (const float4*)sc + (i * 13 + bb.k2) * 9;
        const float4* p3 = (const float4*)sc + (i * 13 + bb.k3) * 9;
        const float4* ps = (const float4*)(ssb + i * 32);
#pragma unroll
        for (int og = 0; og < 8; og++) {
            float4 cA = p0[og], cB = p1[og], cC = p2[og], cD = p3[og];
            float4 sv = ps[og];
            float a0 = acc[4 * og + 0], a1 = acc[4 * og + 1];
            float a2 = acc[4 * og + 2], a3 = acc[4 * og + 3];
            a0 = fmaf(base, sv.x, a0);
            a0 = fmaf(bb.v0, cA.x, a0); a0 = fmaf(bb.v1, cB.x, a0);
            a0 = fmaf(bb.v2, cC.x, a0); a0 = fmaf(bb.v3, cD.x, a0);
            a1 = fmaf(base, sv.y, a1);
            a1 = fmaf(bb.v0, cA.y, a1); a1 = fmaf(bb.v1, cB.y, a1);
            a1 = fmaf(bb.v2, cC.y, a1); a1 = fmaf(bb.v3, cD.y, a1);
            a2 = fmaf(base, sv.z, a2);
            a2 = fmaf(bb.v0, cA.z, a2); a2 = fmaf(bb.v1, cB.z, a2);
            a2 = fmaf(bb.v2, cC.z, a2); a2 = fmaf(bb.v3, cD.z, a2);
            a3 = fmaf(base, sv.w, a3);
            a3 = fmaf(bb.v0, cA.w, a3); a3 = fmaf(bb.v1, cB.w, a3);
            a3 = fmaf(bb.v2, cC.w, a3); a3 = fmaf(bb.v3, cD.w, a3);
            acc[4 * og + 0] = a0; acc[4 * og + 1] = a1;
            acc[4 * og + 2] = a2; acc[4 * og + 3] = a3;
        }
    }
}

// ---------------------------------------------------------------------------
// Main fused kernel: persistent blocks, one thread = one sample.
// ---------------------------------------------------------------------------
__global__ void __launch_bounds__(256, 2)
kan_kernel(const float* __restrict__ coords, float* __restrict__ out, int n) {
    extern __shared__ float smem[];
    {
        float4*       d = (float4*)smem;
        const float4* s = (const float4*)g_scratch;
        for (int idx = threadIdx.x; idx < SCRATCH_FLOATS / 4; idx += blockDim.x)
            d[idx] = s[idx];
    }
    __syncthreads();

    const float* sc0  = smem + OFF_C0;
    const float* sc1  = smem + OFF_C1;
    const float* sc2  = smem + OFF_C2;
    const float* ssb0 = smem + OFF_SB0;
    const float* ssb1 = smem + OFF_SB1;
    const float* ssb2 = smem + OFF_SB2;
    const float  bias = smem[OFF_BIAS];

    for (int b = blockIdx.x * blockDim.x + threadIdx.x; b < n;
         b += gridDim.x * blockDim.x) {
        float2 xy = ((const float2*)coords)[b];
        float xin0[2] = {xy.x, xy.y};

        // Layer 0: 2 -> 32
        float h1[32];
#pragma unroll
        for (int o = 0; o < 32; o++) h1[o] = 0.0f;
        kan_layer32<2>(xin0, h1, sc0, ssb0);

        // Layer 1: 32 -> 32
        float h2[32];
#pragma unroll
        for (int o = 0; o < 32; o++) h2[o] = 0.0f;
        kan_layer32<32>(h1, h2, sc1, ssb1);

        // Layer 2: 32 -> 1
        float logit = bias;
#pragma unroll
        for (int i = 0; i < 32; i++) {
            float x    = h2[i];
            float base = silu_f(x);
            Basis bb   = make_basis(x);
            const float* c = sc2 + i * 16;
            logit = fmaf(ssb2[i], base, logit);
            logit = fmaf(bb.v0, c[bb.k0], logit);
            logit = fmaf(bb.v1, c[bb.k1], logit);
            logit = fmaf(bb.v2, c[bb.k2], logit);
            logit = fmaf(bb.v3, c[bb.k3], logit);
        }

        out[b] = __fdividef(1.0f, 1.0f + __expf(-logit));
    }
}

// ---------------------------------------------------------------------------
// Launch
// ---------------------------------------------------------------------------
extern "C" void kernel_launch(void* const* d_in, const int* in_sizes, int n_in,
                              void* d_out, int out_size) {
    const float* coords = (const float*)d_in[0];
    const float* coef0  = (const float*)d_in[2];
    const float* sb0    = (const float*)d_in[3];
    const float* sp0    = (const float*)d_in[4];
    const float* coef1  = (const float*)d_in[6];
    const float* sb1    = (const float*)d_in[7];
    const float* sp1    = (const float*)d_in[8];
    const float* coef2  = (const float*)d_in[10];
    const float* sb2    = (const float*)d_in[11];
    const float* sp2    = (const float*)d_in[12];
    const float* bias   = (const float*)d_in[13];

    prep_kernel<<<32, 256>>>(coef0, sb0, sp0, coef1, sb1, sp1,
                             coef2, sb2, sp2, bias);

    cudaFuncSetAttribute(kan_kernel,
                         cudaFuncAttributeMaxDynamicSharedMemorySize, SMEM_BYTES);
    kan_kernel<<<296, 256, SMEM_BYTES>>>(coords, (float*)d_out, out_size);
}

// round 9
// speedup vs baseline: 1.2034x; 1.2034x over previous
#include <cuda_runtime.h>
#include <cuda_fp16.h>

// ---------------------------------------------------------------------------
// CoordKAN: 2 -> 32 -> 32 -> 1, cubic B-splines (K=3) on uniform grid G=10.
//
// R3: fp32 smem version is crossbar-bound (L1=80.8%, 163.6us).
// R7: bf16 coefs halve bytes but rel_err 1.8e-3 (coef quantization) fails.
// R8: fp16 coefs (8x finer mantissa -> ~2.2e-4 quant error). The 4-term
// spline dot is computed in half2 via HFMA2 (full-rate fma pipe); only the
// 4-term partials are converted to fp32 (32 F2F per input vs 128 for full
// unpack), master accumulation stays fp32. Rows padded to 18 words so
// divergent-k LDS.64 is conflict-free (18*dk mod 32 never in {0,+-1}).
// ---------------------------------------------------------------------------

// scratch layout (uint32 word offsets)
#define OFF_C0   0        // fp16 [2][13][18 words]   = 468
#define OFF_C1   468      // fp16 [32][13][18 words]  = 7488
#define OFF_C2   7956     // fp32 [32][16]            = 512
#define OFF_SB0  8468     // fp32 [2][32]             = 64
#define OFF_SB1  8532     // fp32 [32][32]            = 1024
#define OFF_SB2  9556     // fp32 [32]                = 32
#define OFF_BIAS 9588
#define SCRATCH_WORDS 9592
#define SMEM_BYTES (SCRATCH_WORDS * 4)

__device__ unsigned g_scratch[SCRATCH_WORDS];

__device__ __forceinline__ unsigned pack_f16_pair(float lo, float hi) {
    __half2 h = __floats2half2_rn(lo, hi);
    return *(unsigned*)&h;
}

__device__ __forceinline__ __half2 u2h(unsigned w) {
    return *(__half2*)&w;
}

// ---------------------------------------------------------------------------
// Prep: fold sp into coef, convert to fp16 pairs, [i][k][o-pairs] stride-18.
// ---------------------------------------------------------------------------
__global__ void prep_kernel(const float* __restrict__ coef0, const float* __restrict__ sb0,
                            const float* __restrict__ sp0,
                            const float* __restrict__ coef1, const float* __restrict__ sb1,
                            const float* __restrict__ sp1,
                            const float* __restrict__ coef2, const float* __restrict__ sb2,
                            const float* __restrict__ sp2,
                            const float* __restrict__ bias) {
    int t = threadIdx.x + blockIdx.x * blockDim.x;
    int T = blockDim.x * gridDim.x;
    // layer1 coef: (32, 32, 13) -> fp16 pairs [i][k][op], row stride 18 words
    for (int idx = t; idx < 32 * 13 * 16; idx += T) {
        int i  = idx / (13 * 16);
        int k  = (idx / 16) % 13;
        int op = idx & 15;
        int o0 = 2 * op, o1 = 2 * op + 1;
        float lo = sp1[i * 32 + o0] * coef1[(i * 32 + o0) * 13 + k];
        float hi = sp1[i * 32 + o1] * coef1[(i * 32 + o1) * 13 + k];
        g_scratch[OFF_C1 + (i * 13 + k) * 18 + op] = pack_f16_pair(lo, hi);
    }
    // layer0 coef: (2, 32, 13)
    for (int idx = t; idx < 2 * 13 * 16; idx += T) {
        int i  = idx / (13 * 16);
        int k  = (idx / 16) % 13;
        int op = idx & 15;
        int o0 = 2 * op, o1 = 2 * op + 1;
        float lo = sp0[i * 32 + o0] * coef0[(i * 32 + o0) * 13 + k];
        float hi = sp0[i * 32 + o1] * coef0[(i * 32 + o1) * 13 + k];
        g_scratch[OFF_C0 + (i * 13 + k) * 18 + op] = pack_f16_pair(lo, hi);
    }
    // layer2 coef: (32, 1, 13) -> fp32 [i][16]
    for (int idx = t; idx < 32 * 13; idx += T) {
        int i = idx / 13;
        int k = idx % 13;
        g_scratch[OFF_C2 + i * 16 + k] = __float_as_uint(sp2[i] * coef2[i * 13 + k]);
    }
    for (int idx = t; idx < 2 * 32; idx += T)  g_scratch[OFF_SB0 + idx] = __float_as_uint(sb0[idx]);
    for (int idx = t; idx < 32 * 32; idx += T) g_scratch[OFF_SB1 + idx] = __float_as_uint(sb1[idx]);
    for (int idx = t; idx < 32; idx += T)      g_scratch[OFF_SB2 + idx] = __float_as_uint(sb2[idx]);
    if (t == 0) g_scratch[OFF_BIAS] = __float_as_uint(bias[0]);
}

// ---------------------------------------------------------------------------
// Device helpers
// ---------------------------------------------------------------------------
__device__ __forceinline__ float silu_f(float x) {
    return x * __fdividef(1.0f, 1.0f + __expf(-x));
}

struct Basis {
    float v0, v1, v2, v3;
    int   k0, k1, k2, k3;
};

__device__ __forceinline__ Basis make_basis(float x) {
    float u  = fmaf(x, 10.0f, 3.0f);
    float mf = floorf(u);
    float t  = u - mf;
    int   m  = (int)mf;
    int   j0 = m - 3;
    float t2 = t * t;
    float t3 = t2 * t;
    float omt = 1.0f - t;
    Basis b;
    b.v0 = omt * omt * omt * (1.0f / 6.0f);
    b.v1 = fmaf(3.0f, t3, fmaf(-6.0f, t2, 4.0f)) * (1.0f / 6.0f);
    b.v2 = fmaf(-3.0f, t3, fmaf(3.0f, t2, fmaf(3.0f, t, 1.0f))) * (1.0f / 6.0f);
    b.v3 = t3 * (1.0f / 6.0f);
    bool inr = (m >= 0) && (m <= 15);
    if (!inr || j0 < 0     || j0 > 12)     b.v0 = 0.0f;
    if (!inr || j0 + 1 < 0 || j0 + 1 > 12) b.v1 = 0.0f;
    if (!inr || j0 + 2 < 0 || j0 + 2 > 12) b.v2 = 0.0f;
    if (!inr || j0 + 3 < 0 || j0 + 3 > 12) b.v3 = 0.0f;
    b.k0 = min(max(j0, 0), 12);
    b.k1 = min(max(j0 + 1, 0), 12);
    b.k2 = min(max(j0 + 2, 0), 12);
    b.k3 = min(max(j0 + 3, 0), 12);
    return b;
}

// One KAN layer with 32 outputs, fp16 coef rows (18 u32 per [i][k] row).
// 4-term spline dots in half2 (HFMA2), partials promoted to fp32 per (i,op).
template <int NI>
__device__ __forceinline__ void kan_layer_h(const float* xin, float* acc,
                                            const unsigned* __restrict__ cc,
                                            const float* __restrict__ ssb) {
#pragma unroll
    for (int i = 0; i < NI; i++) {
        float x    = xin[i];
        float base = silu_f(x);
        Basis bb   = make_basis(x);
        __half2 hv0 = __float2half2_rn(bb.v0);
        __half2 hv1 = __float2half2_rn(bb.v1);
        __half2 hv2 = __float2half2_rn(bb.v2);
        __half2 hv3 = __float2half2_rn(bb.v3);
        const uint2* q0 = (const uint2*)cc + (i * 13 + bb.k0) * 9;  // 18 words = 9 uint2
        const uint2* q1 = (const uint2*)cc + (i * 13 + bb.k1) * 9;
        const uint2* q2 = (const uint2*)cc + (i * 13 + bb.k2) * 9;
        const uint2* q3 = (const uint2*)cc + (i * 13 + bb.k3) * 9;
        const float4* ps = (const float4*)(ssb + i * 32);
#pragma unroll
        for (int og = 0; og < 8; og++) {
            uint2 wA = q0[og], wB = q1[og], wC = q2[og], wD = q3[og];
            float4 sv = ps[og];
            // 4-term dot in half2 (two o's per lane of the half2)
            __half2 p0 = __hmul2(hv0, u2h(wA.x));
            p0 = __hfma2(hv1, u2h(wB.x), p0);
            p0 = __hfma2(hv2, u2h(wC.x), p0);
            p0 = __hfma2(hv3, u2h(wD.x), p0);
            __half2 p1 = __hmul2(hv0, u2h(wA.y));
            p1 = __hfma2(hv1, u2h(wB.y), p1);
            p1 = __hfma2(hv2, u2h(wC.y), p1);
            p1 = __hfma2(hv3, u2h(wD.y), p1);
            float2 f0 = __half22float2(p0);
            float2 f1 = __half22float2(p1);
            float a0 = acc[4 * og + 0], a1 = acc[4 * og + 1];
            float a2 = acc[4 * og + 2], a3 = acc[4 * og + 3];
            a0 += f0.x; a0 = fmaf(base, sv.x, a0);
            a1 += f0.y; a1 = fmaf(base, sv.y, a1);
            a2 += f1.x; a2 = fmaf(base, sv.z, a2);
            a3 += f1.y; a3 = fmaf(base, sv.w, a3);
            acc[4 * og + 0] = a0; acc[4 * og + 1] = a1;
            acc[4 * og + 2] = a2; acc[4 * og + 3] = a3;
        }
    }
}

// ---------------------------------------------------------------------------
// Main fused kernel: persistent blocks, one thread = one sample.
// ---------------------------------------------------------------------------
__global__ void __launch_bounds__(256, 2)
kan_kernel(const float* __restrict__ coords, float* __restrict__ out, int n) {
    extern __shared__ unsigned smem[];
    {
        uint4*       d = (uint4*)smem;
        const uint4* s = (const uint4*)g_scratch;
        for (int idx = threadIdx.x; idx < SCRATCH_WORDS / 4; idx += blockDim.x)
            d[idx] = s[idx];
    }
    __syncthreads();

    const unsigned* sc0 = smem + OFF_C0;
    const unsigned* sc1 = smem + OFF_C1;
    const float* sc2  = (const float*)(smem + OFF_C2);
    const float* ssb0 = (const float*)(smem + OFF_SB0);
    const float* ssb1 = (const float*)(smem + OFF_SB1);
    const float* ssb2 = (const float*)(smem + OFF_SB2);
    const float  bias = __uint_as_float(smem[OFF_BIAS]);

    for (int b = blockIdx.x * blockDim.x + threadIdx.x; b < n;
         b += gridDim.x * blockDim.x) {
        float2 xy = ((const float2*)coords)[b];
        float xin0[2] = {xy.x, xy.y};

        // Layer 0: 2 -> 32
        float h1[32];
#pragma unroll
        for (int o = 0; o < 32; o++) h1[o] = 0.0f;
        kan_layer_h<2>(xin0, h1, sc0, ssb0);

        // Layer 1: 32 -> 32
        float h2[32];
#pragma unroll
        for (int o = 0; o < 32; o++) h2[o] = 0.0f;
        kan_layer_h<32>(h1, h2, sc1, ssb1);

        // Layer 2: 32 -> 1 (fp32 coefs; [i][16] layout, divergent k within a
        // 16-word row -> 13 distinct banks, conflict-light)
        float logit = bias;
#pragma unroll
        for (int i = 0; i < 32; i++) {
            float x    = h2[i];
            float base = silu_f(x);
            Basis bb   = make_basis(x);
            const float* c = sc2 + i * 16;
            logit = fmaf(ssb2[i], base, logit);
            logit = fmaf(bb.v0, c[bb.k0], logit);
            logit = fmaf(bb.v1, c[bb.k1], logit);
            logit = fmaf(bb.v2, c[bb.k2], logit);
            logit = fmaf(bb.v3, c[bb.k3], logit);
        }

        out[b] = __fdividef(1.0f, 1.0f + __expf(-logit));
    }
}

// ---------------------------------------------------------------------------
// Launch
// ---------------------------------------------------------------------------
extern "C" void kernel_launch(void* const* d_in, const int* in_sizes, int n_in,
                              void* d_out, int out_size) {
    const float* coords = (const float*)d_in[0];
    const float* coef0  = (const float*)d_in[2];
    const float* sb0    = (const float*)d_in[3];
    const float* sp0    = (const float*)d_in[4];
    const float* coef1  = (const float*)d_in[6];
    const float* sb1    = (const float*)d_in[7];
    const float* sp1    = (const float*)d_in[8];
    const float* coef2  = (const float*)d_in[10];
    const float* sb2    = (const float*)d_in[11];
    const float* sp2    = (const float*)d_in[12];
    const float* bias   = (const float*)d_in[13];

    prep_kernel<<<32, 256>>>(coef0, sb0, sp0, coef1, sb1, sp1,
                             coef2, sb2, sp2, bias);

    cudaFuncSetAttribute(kan_kernel,
                         cudaFuncAttributeMaxDynamicSharedMemorySize, SMEM_BYTES);
    kan_kernel<<<296, 256, SMEM_BYTES>>>(coords, (float*)d_out, out_size);
}

// round 12
// speedup vs baseline: 1.2057x; 1.0019x over previous
#include <cuda_runtime.h>
#include <cuda_fp16.h>

// ---------------------------------------------------------------------------
// CoordKAN: 2 -> 32 -> 32 -> 1, cubic B-splines (K=3) on uniform grid G=10.
//
// R3: fp32 smem version crossbar-bound (L1=80.8%, 163.6us).
// R8: fp16 coefs + HFMA2 partials, fp32 master acc -> 135.9us, rel_err 4.7e-4.
//     ncu: no pipe >50%, issue=47%, occ=22% (16 warps/SM, reg-ceiling) =>
//     latency-bound.
// R10: occupancy 2->3 blocks/SM: h1 moved to smem ([i][tid], conflict-free),
//      __launch_bounds__(256,3) (targets 85 regs), grid 444.
// ---------------------------------------------------------------------------

// scratch layout (uint32 word offsets)
#define OFF_C0   0        // fp16 [2][13][18 words]   = 468
#define OFF_C1   468      // fp16 [32][13][18 words]  = 7488
#define OFF_C2   7956     // fp32 [32][16]            = 512
#define OFF_SB0  8468     // fp32 [2][32]             = 64
#define OFF_SB1  8532     // fp32 [32][32]            = 1024
#define OFF_SB2  9556     // fp32 [32]                = 32
#define OFF_BIAS 9588
#define SCRATCH_WORDS 9592
#define SMEM_BYTES (SCRATCH_WORDS * 4)

// per-block h1 buffer: [32][256] floats, after the weight scratch
#define HBUF_WORDS (32 * 256)
#define DYN_SMEM_BYTES (SMEM_BYTES + HBUF_WORDS * 4)

__device__ unsigned g_scratch[SCRATCH_WORDS];

__device__ __forceinline__ unsigned pack_f16_pair(float lo, float hi) {
    __half2 h = __floats2half2_rn(lo, hi);
    return *(unsigned*)&h;
}

__device__ __forceinline__ __half2 u2h(unsigned w) {
    return *(__half2*)&w;
}

// ---------------------------------------------------------------------------
// Prep: fold sp into coef, convert to fp16 pairs, [i][k][o-pairs] stride-18.
// ---------------------------------------------------------------------------
__global__ void prep_kernel(const float* __restrict__ coef0, const float* __restrict__ sb0,
                            const float* __restrict__ sp0,
                            const float* __restrict__ coef1, const float* __restrict__ sb1,
                            const float* __restrict__ sp1,
                            const float* __restrict__ coef2, const float* __restrict__ sb2,
                            const float* __restrict__ sp2,
                            const float* __restrict__ bias) {
    int t = threadIdx.x + blockIdx.x * blockDim.x;
    int T = blockDim.x * gridDim.x;
    // layer1 coef: (32, 32, 13) -> fp16 pairs [i][k][op], row stride 18 words
    for (int idx = t; idx < 32 * 13 * 16; idx += T) {
        int i  = idx / (13 * 16);
        int k  = (idx / 16) % 13;
        int op = idx & 15;
        int o0 = 2 * op, o1 = 2 * op + 1;
        float lo = sp1[i * 32 + o0] * coef1[(i * 32 + o0) * 13 + k];
        float hi = sp1[i * 32 + o1] * coef1[(i * 32 + o1) * 13 + k];
        g_scratch[OFF_C1 + (i * 13 + k) * 18 + op] = pack_f16_pair(lo, hi);
    }
    // layer0 coef: (2, 32, 13)
    for (int idx = t; idx < 2 * 13 * 16; idx += T) {
        int i  = idx / (13 * 16);
        int k  = (idx / 16) % 13;
        int op = idx & 15;
        int o0 = 2 * op, o1 = 2 * op + 1;
        float lo = sp0[i * 32 + o0] * coef0[(i * 32 + o0) * 13 + k];
        float hi = sp0[i * 32 + o1] * coef0[(i * 32 + o1) * 13 + k];
        g_scratch[OFF_C0 + (i * 13 + k) * 18 + op] = pack_f16_pair(lo, hi);
    }
    // layer2 coef: (32, 1, 13) -> fp32 [i][16]
    for (int idx = t; idx < 32 * 13; idx += T) {
        int i = idx / 13;
        int k = idx % 13;
        g_scratch[OFF_C2 + i * 16 + k] = __float_as_uint(sp2[i] * coef2[i * 13 + k]);
    }
    for (int idx = t; idx < 2 * 32; idx += T)  g_scratch[OFF_SB0 + idx] = __float_as_uint(sb0[idx]);
    for (int idx = t; idx < 32 * 32; idx += T) g_scratch[OFF_SB1 + idx] = __float_as_uint(sb1[idx]);
    for (int idx = t; idx < 32; idx += T)      g_scratch[OFF_SB2 + idx] = __float_as_uint(sb2[idx]);
    if (t == 0) g_scratch[OFF_BIAS] = __float_as_uint(bias[0]);
}

// ---------------------------------------------------------------------------
// Device helpers
// ---------------------------------------------------------------------------
__device__ __forceinline__ float silu_f(float x) {
    return x * __fdividef(1.0f, 1.0f + __expf(-x));
}

struct Basis {
    float v0, v1, v2, v3;
    int   k0, k1, k2, k3;
};

__device__ __forceinline__ Basis make_basis(float x) {
    float u  = fmaf(x, 10.0f, 3.0f);
    float mf = floorf(u);
    float t  = u - mf;
    int   m  = (int)mf;
    int   j0 = m - 3;
    float t2 = t * t;
    float t3 = t2 * t;
    float omt = 1.0f - t;
    Basis b;
    b.v0 = omt * omt * omt * (1.0f / 6.0f);
    b.v1 = fmaf(3.0f, t3, fmaf(-6.0f, t2, 4.0f)) * (1.0f / 6.0f);
    b.v2 = fmaf(-3.0f, t3, fmaf(3.0f, t2, fmaf(3.0f, t, 1.0f))) * (1.0f / 6.0f);
    b.v3 = t3 * (1.0f / 6.0f);
    bool inr = (m >= 0) && (m <= 15);
    if (!inr || j0 < 0     || j0 > 12)     b.v0 = 0.0f;
    if (!inr || j0 + 1 < 0 || j0 + 1 > 12) b.v1 = 0.0f;
    if (!inr || j0 + 2 < 0 || j0 + 2 > 12) b.v2 = 0.0f;
    if (!inr || j0 + 3 < 0 || j0 + 3 > 12) b.v3 = 0.0f;
    b.k0 = min(max(j0, 0), 12);
    b.k1 = min(max(j0 + 1, 0), 12);
    b.k2 = min(max(j0 + 2, 0), 12);
    b.k3 = min(max(j0 + 3, 0), 12);
    return b;
}

// Accumulate the contribution of one input x (index i) into acc[32].
// Coef rows are fp16 pairs, 18 u32 per [i][k] row; 4-term spline dots in
// half2 (HFMA2), partials promoted to fp32 per (i, o-pair).
__device__ __forceinline__ void kan_accum_input(float x, int i, float* acc,
                                                const unsigned* __restrict__ cc,
                                                const float* __restrict__ ssb) {
    float base = silu_f(x);
    Basis bb   = make_basis(x);
    __half2 hv0 = __float2half2_rn(bb.v0);
    __half2 hv1 = __float2half2_rn(bb.v1);
    __half2 hv2 = __float2half2_rn(bb.v2);
    __half2 hv3 = __float2half2_rn(bb.v3);
    const uint2* q0 = (const uint2*)cc + (i * 13 + bb.k0) * 9;  // 18 words = 9 uint2
    const uint2* q1 = (const uint2*)cc + (i * 13 + bb.k1) * 9;
    const uint2* q2 = (const uint2*)cc + (i * 13 + bb.k2) * 9;
    const uint2* q3 = (const uint2*)cc + (i * 13 + bb.k3) * 9;
    const float4* ps = (const float4*)(ssb + i * 32);
#pragma unroll
    for (int og = 0; og < 8; og++) {
        uint2 wA = q0[og], wB = q1[og], wC = q2[og], wD = q3[og];
        float4 sv = ps[og];
        __half2 p0 = __hmul2(hv0, u2h(wA.x));
        p0 = __hfma2(hv1, u2h(wB.x), p0);
        p0 = __hfma2(hv2, u2h(wC.x), p0);
        p0 = __hfma2(hv3, u2h(wD.x), p0);
        __half2 p1 = __hmul2(hv0, u2h(wA.y));
        p1 = __hfma2(hv1, u2h(wB.y), p1);
        p1 = __hfma2(hv2, u2h(wC.y), p1);
        p1 = __hfma2(hv3, u2h(wD.y), p1);
        float2 f0 = __half22float2(p0);
        float2 f1 = __half22float2(p1);
        float a0 = acc[4 * og + 0], a1 = acc[4 * og + 1];
        float a2 = acc[4 * og + 2], a3 = acc[4 * og + 3];
        a0 += f0.x; a0 = fmaf(base, sv.x, a0);
        a1 += f0.y; a1 = fmaf(base, sv.y, a1);
        a2 += f1.x; a2 = fmaf(base, sv.z, a2);
        a3 += f1.y; a3 = fmaf(base, sv.w, a3);
        acc[4 * og + 0] = a0; acc[4 * og + 1] = a1;
        acc[4 * og + 2] = a2; acc[4 * og + 3] = a3;
    }
}

// ---------------------------------------------------------------------------
// Main fused kernel: persistent blocks, one thread = one sample.
// h1 parked in smem ([i][tid], lane-consecutive -> conflict-free) so the
// layer-1 register peak is just acc[32] + temps -> 3 blocks/SM fit.
// ---------------------------------------------------------------------------
__global__ void __launch_bounds__(256, 3)
kan_kernel(const float* __restrict__ coords, float* __restrict__ out, int n) {
    extern __shared__ unsigned smem[];
    {
        uint4*       d = (uint4*)smem;
        const uint4* s = (const uint4*)g_scratch;
        for (int idx = threadIdx.x; idx < SCRATCH_WORDS / 4; idx += blockDim.x)
            d[idx] = s[idx];
    }
    __syncthreads();

    const unsigned* sc0 = smem + OFF_C0;
    const unsigned* sc1 = smem + OFF_C1;
    const float* sc2  = (const float*)(smem + OFF_C2);
    const float* ssb0 = (const float*)(smem + OFF_SB0);
    const float* ssb1 = (const float*)(smem + OFF_SB1);
    const float* ssb2 = (const float*)(smem + OFF_SB2);
    const float  bias = __uint_as_float(smem[OFF_BIAS]);
    float* hbuf = (float*)(smem + SCRATCH_WORDS);   // [32][256]
    const int tid = threadIdx.x;

    for (int b = blockIdx.x * blockDim.x + tid; b < n;
         b += gridDim.x * blockDim.x) {
        float2 xy = ((const float2*)coords)[b];

        // Layer 0: 2 -> 32, acc in regs (short-lived), park result in smem
        {
            float h1[32];
#pragma unroll
            for (int o = 0; o < 32; o++) h1[o] = 0.0f;
            kan_accum_input(xy.x, 0, h1, sc0, ssb0);
            kan_accum_input(xy.y, 1, h1, sc0, ssb0);
#pragma unroll
            for (int o = 0; o < 32; o++) hbuf[o * 256 + tid] = h1[o];
        }

        // Layer 1: 32 -> 32, inputs streamed from smem
        float h2[32];
#pragma unroll
        for (int o = 0; o < 32; o++) h2[o] = 0.0f;
#pragma unroll
        for (int i = 0; i < 32; i++) {
            float x = hbuf[i * 256 + tid];
            kan_accum_input(x, i, h2, sc1, ssb1);
        }

        // Layer 2: 32 -> 1 (fp32 coefs; [i][16] layout)
        float logit = bias;
#pragma unroll
        for (int i = 0; i < 32; i++) {
            float x    = h2[i];
            float base = silu_f(x);
            Basis bb   = make_basis(x);
            const float* c = sc2 + i * 16;
            logit = fmaf(ssb2[i], base, logit);
            logit = fmaf(bb.v0, c[bb.k0], logit);
            logit = fmaf(bb.v1, c[bb.k1], logit);
            logit = fmaf(bb.v2, c[bb.k2], logit);
            logit = fmaf(bb.v3, c[bb.k3], logit);
        }

        out[b] = __fdividef(1.0f, 1.0f + __expf(-logit));
    }
}

// ---------------------------------------------------------------------------
// Launch
// ---------------------------------------------------------------------------
extern "C" void kernel_launch(void* const* d_in, const int* in_sizes, int n_in,
                              void* d_out, int out_size) {
    const float* coords = (const float*)d_in[0];
    const float* coef0  = (const float*)d_in[2];
    const float* sb0    = (const float*)d_in[3];
    const float* sp0    = (const float*)d_in[4];
    const float* coef1  = (const float*)d_in[6];
    const float* sb1    = (const float*)d_in[7];
    const float* sp1    = (const float*)d_in[8];
    const float* coef2  = (const float*)d_in[10];
    const float* sb2    = (const float*)d_in[11];
    const float* sp2    = (const float*)d_in[12];
    const float* bias   = (const float*)d_in[13];

    prep_kernel<<<32, 256>>>(coef0, sb0, sp0, coef1, sb1, sp1,
                             coef2, sb2, sp2, bias);

    cudaFuncSetAttribute(kan_kernel,
                         cudaFuncAttributeMaxDynamicSharedMemorySize, DYN_SMEM_BYTES);
    kan_kernel<<<444, 256, DYN_SMEM_BYTES>>>(coords, (float*)d_out, out_size);
}